// round 9
// baseline (speedup 1.0000x reference)
#include <cuda_runtime.h>
#include <cuda_fp16.h>
#include <cstdint>

// ---------------------------------------------------------------------------
// RingNet: SAT box features -> folded GEMM1 -> ReLU -> folded GEMM2.
// A single fp16, B hi+lo fp16 (lo-correction on even K-chunks only; odd
// chunks don't even stage the lo block). Operands pre-packed into
// chunk-contiguous XOR-swizzled blocks, staged by cp.async.bulk rings.
// ---------------------------------------------------------------------------

namespace {
constexpr int Bn = 4, Cn = 96, Hn = 128, Wn = 128;
constexpr int HWn = Hn * Wn;           // 16384
constexpr int Mtot = Bn * HWn;         // 65536
constexpr int K1 = 1248, N1 = 512, N2 = 96;
constexpr int NC1 = K1 / 32;           // 39
constexpr int NC2 = N1 / 32;           // 16
constexpr int SATR = 129, SATC = 132;
constexpr float BN_EPS = 1e-5f;
constexpr int A_TS = 8192;             // 32k x 256B (128 m)
constexpr int BH_TS = 16384;           // 256n x 64B (hi OR lo block)
constexpr int STG1 = A_TS + 2 * BH_TS; // 40960
constexpr int B2_TS = 12288;           // 96n x 128B hi|lo (GEMM2, unchanged)
constexpr int STG2 = A_TS + B2_TS;     // 20480
constexpr int NSTG = 4;
constexpr int NSAT = Bn * Cn * SATR;   // 49536
constexpr int PRE_FOLD_BLKS = N1 + N2; // 608
}

// -------------------- device scratch ----------------------------------------
__device__ float   g_sat[(size_t)Bn * Cn * SATR * SATC];            // 26 MB
__device__ uint8_t g_phiB[(size_t)(Mtot / 128) * NC1 * A_TS];       // 164 MB
__device__ uint8_t g_W1p[(size_t)NC1 * 2 * 2 * BH_TS];              // 2.5 MB
__device__ uint8_t g_h1B[(size_t)(Mtot / 128) * NC2 * A_TS];        // 67 MB
__device__ uint8_t g_W2p[(size_t)NC2 * B2_TS];                      // 196 KB
__device__ float   g_b1f[N1], g_b2f[N2];

// -------------------- helpers ------------------------------------------------
__device__ __forceinline__ uint32_t smem_u32(const void* p) {
    uint32_t a;
    asm("{ .reg .u64 t; cvta.to.shared.u64 t, %1; cvt.u32.u64 %0, t; }" : "=r"(a) : "l"(p));
    return a;
}
__device__ __forceinline__ void bulk_g2s(uint32_t dst, const void* src, uint32_t bytes,
                                         uint32_t mbar) {
    asm volatile(
        "cp.async.bulk.shared::cluster.global.mbarrier::complete_tx::bytes [%0], [%1], %2, [%3];"
        :: "r"(dst), "l"(src), "r"(bytes), "r"(mbar) : "memory");
}
#define MBAR_INIT(a, n) \
    asm volatile("mbarrier.init.shared.b64 [%0], %1;" :: "r"(a), "r"((uint32_t)(n)) : "memory")
#define MBAR_EXPECT_TX(a, n) \
    asm volatile("mbarrier.arrive.expect_tx.shared.b64 _, [%0], %1;" \
        :: "r"(a), "r"((uint32_t)(n)) : "memory")
#define MBAR_WAIT(a, p) do { \
    uint32_t _m = (a), _p = (uint32_t)(p), _d; \
    asm volatile("{\n\t.reg .pred q;\n\t" \
        "mbarrier.try_wait.parity.acquire.cta.shared::cta.b64 q, [%1], %2;\n\t" \
        "selp.b32 %0, 1, 0, q;\n\t}" : "=r"(_d) : "r"(_m), "r"(_p) : "memory"); \
    if (!_d) { \
        asm volatile("{\n\t.reg .pred Q;\n\tWL_%=:\n\t" \
            "mbarrier.try_wait.parity.acquire.cta.shared::cta.b64 Q, [%0], %1, 0x989680;\n\t" \
            "@Q bra.uni WD_%=;\n\tbra.uni WL_%=;\n\tWD_%=:\n\t}" \
            :: "r"(_m), "r"(_p) : "memory"); \
    } } while (0)
__device__ __forceinline__ void mma_h(float* c, const uint32_t* a, const uint32_t* b) {
    asm volatile(
        "mma.sync.aligned.m16n8k16.row.col.f32.f16.f16.f32 "
        "{%0,%1,%2,%3},{%4,%5,%6,%7},{%8,%9},{%0,%1,%2,%3};\n"
        : "+f"(c[0]), "+f"(c[1]), "+f"(c[2]), "+f"(c[3])
        : "r"(a[0]), "r"(a[1]), "r"(a[2]), "r"(a[3]), "r"(b[0]), "r"(b[1]));
}
__device__ __forceinline__ void ldsm4(uint32_t& a, uint32_t& b, uint32_t& c, uint32_t& d,
                                      uint32_t addr) {
    asm volatile("ldmatrix.sync.aligned.m8n8.x4.shared.b16 {%0,%1,%2,%3},[%4];"
        : "=r"(a), "=r"(b), "=r"(c), "=r"(d) : "r"(addr));
}
__device__ __forceinline__ void ldsm4t(uint32_t& a, uint32_t& b, uint32_t& c, uint32_t& d,
                                       uint32_t addr) {
    asm volatile("ldmatrix.sync.aligned.m8n8.x4.trans.shared.b16 {%0,%1,%2,%3},[%4];"
        : "=r"(a), "=r"(b), "=r"(c), "=r"(d) : "r"(addr));
}

// -------------------- fused: weight folding/packing + SAT row pass -----------
__global__ void k_pre(const float* __restrict__ x,
                      const float* __restrict__ W1, const float* __restrict__ b1,
                      const float* __restrict__ ga1, const float* __restrict__ be1,
                      const float* __restrict__ mu1, const float* __restrict__ va1,
                      const float* __restrict__ W2, const float* __restrict__ b2,
                      const float* __restrict__ ga2, const float* __restrict__ be2,
                      const float* __restrict__ mu2, const float* __restrict__ va2) {
    int tid = threadIdx.x;
    if (blockIdx.x >= PRE_FOLD_BLKS) {
        // ---- SAT row pass ----
        int idx = (blockIdx.x - PRE_FOLD_BLKS) * 256 + tid;
        if (idx >= NSAT) return;
        int img = idx / SATR, r = idx % SATR;
        float* S = g_sat + (size_t)img * SATR * SATC;
        if (r == 0) { for (int cx = 0; cx <= 128; cx++) S[cx] = 0.f; }
        else {
            const float* row = x + (size_t)img * HWn + (size_t)(r - 1) * Wn;
            float* Sr = S + (size_t)r * SATC;
            Sr[0] = 0.f;
            float acc = 0.f;
            for (int xx = 0; xx < Wn; xx++) { acc += row[xx]; Sr[xx + 1] = acc; }
        }
        return;
    }
    // ---- weight folds ----
    float part = 0.f;
    if (blockIdx.x < N1) {
        int o = blockIdx.x;
        int nb = o >> 8, nlo = o & 255;
        int swz = (nlo >> 1) & 3;
        for (int k = tid; k < K1; k += 256) {
            float s = ga1[k] * rsqrtf(va1[k] + BN_EPS);
            float w = W1[(size_t)o * K1 + k];
            part += w * (be1[k] - mu1[k] * s);
            float wb = w * s;
            if (k < K1 - 96) {
                float s2 = ga1[k + 96] * rsqrtf(va1[k + 96] + BN_EPS);
                wb -= W1[(size_t)o * K1 + k + 96] * s2;
            }
            __half hi = __float2half_rn(wb);
            __half lo = __float2half_rn(wb - __half2float(hi));
            int ck = k >> 5, u = (k >> 3) & 3, byo = (k & 7) * 2;
            // layout: [ck][nb][hi 16KB][lo 16KB], 64B rows
            size_t base = (size_t)ck * (4 * BH_TS) + (size_t)nb * (2 * BH_TS)
                        + (size_t)nlo * 64 + (size_t)((u ^ swz) << 4) + byo;
            *(__half*)(g_W1p + base) = hi;
            *(__half*)(g_W1p + base + BH_TS) = lo;
        }
    } else {
        int o = blockIdx.x - N1;       // 0..95
        int nsw = o & 7;
        for (int k = tid; k < N1; k += 256) {
            float s = ga2[k] * rsqrtf(va2[k] + BN_EPS);
            float w = W2[(size_t)o * N1 + k];
            part += w * (be2[k] - mu2[k] * s);
            float wf = w * s;
            __half hi = __float2half_rn(wf);
            __half lo = __float2half_rn(wf - __half2float(hi));
            int ck = k >> 5, uh = (k >> 3) & 3, byo = (k & 7) * 2;
            size_t base = (size_t)ck * B2_TS + (size_t)o * 128;
            *(__half*)(g_W2p + base + ((uh ^ nsw) << 4) + byo) = hi;
            *(__half*)(g_W2p + base + (((uh + 4) ^ nsw) << 4) + byo) = lo;
        }
    }
    __shared__ float red[256];
    red[tid] = part; __syncthreads();
    for (int s = 128; s > 0; s >>= 1) { if (tid < s) red[tid] += red[tid + s]; __syncthreads(); }
    if (tid == 0) {
        if (blockIdx.x < N1) g_b1f[blockIdx.x] = b1[blockIdx.x] + red[0];
        else g_b2f[blockIdx.x - N1] = b2[blockIdx.x - N1] + red[0];
    }
}

// -------------------- SAT column pass -----------------------------------------
__global__ void k_sat_cols() {
    int idx = blockIdx.x * blockDim.x + threadIdx.x;
    if (idx >= NSAT) return;
    int img = idx / SATR, cc = idx % SATR;
    float* S = g_sat + (size_t)img * SATR * SATC;
    float acc = 0.f;
    for (int r = 1; r <= 128; r++) {
        acc += S[(size_t)r * SATC + cc];
        S[(size_t)r * SATC + cc] = acc;
    }
}

// -------------------- features (R6 2-pixel version) ---------------------------
__global__ void k_features(const float* __restrict__ x) {
    int j = blockIdx.y;                           // 0..12
    int m = blockIdx.x * 512 + threadIdx.x * 2;
    int b = m >> 14, pix = m & (HWn - 1), y = pix >> 7, xx = pix & 127;
    int mtile = m >> 7, mloc = m & 127;
    uint32_t ub = (uint32_t)(mloc >> 3);
    size_t outm = (size_t)mtile * ((size_t)NC1 * A_TS) + (size_t)(mloc & 7) * 2;

    if (j == 0) {
        const float* p = x + (size_t)b * Cn * HWn + pix;
        #pragma unroll 4
        for (int c = 0; c < 96; c++) {
            float v0 = p[(size_t)c * HWn], v1 = p[(size_t)c * HWn + 1];
            size_t off = outm + (size_t)(c >> 5) * A_TS + (size_t)(c & 31) * 256
                       + (size_t)((ub ^ (uint32_t)(c & 7)) << 4);
            *(__half2*)(g_phiB + off) = __floats2half2_rn(v0, v1);
        }
    } else {
        int rlo = max(y - j, 0), rhi = min(y + j + 1, 128);
        int cl0 = max(xx - j, 0), ch0 = min(xx + j + 1, 128);
        int cl1 = max(xx + 1 - j, 0), ch1 = min(xx + j + 2, 128);
        int ohh0 = rhi * SATC + ch0, olh0 = rlo * SATC + ch0;
        int ohl0 = rhi * SATC + cl0, oll0 = rlo * SATC + cl0;
        int ohh1 = rhi * SATC + ch1, olh1 = rlo * SATC + ch1;
        int ohl1 = rhi * SATC + cl1, oll1 = rlo * SATC + cl1;
        const float* Sb = g_sat + (size_t)b * Cn * (SATR * SATC);
        #pragma unroll 2
        for (int c = 0; c < 96; c++) {
            const float* S = Sb + (size_t)c * (SATR * SATC);
            float v0 = S[ohh0] - S[olh0] - S[ohl0] + S[oll0];
            float v1 = S[ohh1] - S[olh1] - S[ohl1] + S[oll1];
            int k = j * 96 + c;
            size_t off = outm + (size_t)(k >> 5) * A_TS + (size_t)(k & 31) * 256
                       + (size_t)((ub ^ (uint32_t)(k & 7)) << 4);
            *(__half2*)(g_phiB + off) = __floats2half2_rn(v0, v1);
        }
    }
}

// -------------------- GEMM1: bulk ring; B-lo staged/used on even chunks -------
// C[128m, 256n] per CTA, 8 warps (2m x 4n). Epilogue: smem transpose ->
// packed h1 blocks (same format as phi).
__global__ void __launch_bounds__(256, 1) k_gemm1() {
    constexpr int OFF_BIAS = NSTG * STG1;          // 163840
    constexpr int OFF_MBAR = OFF_BIAS + 1024;
    constexpr int RS_E = 272;                      // epilogue row stride
    extern __shared__ char smem[];
    uint32_t sb = smem_u32(smem);
    float* s_bias = (float*)(smem + OFF_BIAS);
    int tid = threadIdx.x, wid = tid >> 5, lane = tid & 31;
    int grp = lane >> 3, rr = lane & 7;
    int wm = (wid & 1) * 64, wn = (wid >> 1) * 64;
    int nb = blockIdx.x, mtile = blockIdx.y;       // x fast -> L2 phi pairing
    int n0 = nb * 256;

    if (tid == 0) {
        #pragma unroll
        for (int s = 0; s < NSTG; s++) MBAR_INIT(sb + OFF_MBAR + s * 8, 1);
        asm volatile("fence.proxy.async.shared::cta;" ::: "memory");
    }
    for (int i = tid; i < 256; i += 256) s_bias[i] = g_b1f[n0 + i];
    __syncthreads();

    const uint8_t* phiB = g_phiB + (size_t)mtile * ((size_t)NC1 * A_TS);
    const uint8_t* w1p  = g_W1p + (size_t)nb * (2 * BH_TS);

    if (tid == 0) {
        #pragma unroll
        for (int s = 0; s < NSTG; s++) {
            uint32_t mb = sb + OFF_MBAR + s * 8;
            uint32_t bby = (s & 1) ? BH_TS : 2 * BH_TS;   // odd chunk: hi only
            MBAR_EXPECT_TX(mb, A_TS + bby);
            bulk_g2s(sb + s * STG1, phiB + (size_t)s * A_TS, A_TS, mb);
            bulk_g2s(sb + s * STG1 + A_TS, w1p + (size_t)s * (4 * BH_TS), bby, mb);
        }
    }

    uint32_t aoff[2][4], bho[2][4];
    #pragma unroll
    for (int ks = 0; ks < 2; ks++) {
        #pragma unroll
        for (int mt = 0; mt < 4; mt++) {
            int row = ks * 16 + (grp >> 1) * 8 + rr;
            int u = (wm >> 3) + mt * 2 + (grp & 1);
            aoff[ks][mt] = (uint32_t)(row * 256 + ((u ^ rr) << 4));
        }
        #pragma unroll
        for (int p = 0; p < 4; p++) {
            int n = wn + p * 16 + (grp >> 1) * 8 + rr;
            int uh = ks * 2 + (grp & 1);
            bho[ks][p] = (uint32_t)(n * 64 + ((uh ^ ((n >> 1) & 3)) << 4));
        }
    }

    float acc[4][8][4];
    #pragma unroll
    for (int mt = 0; mt < 4; mt++)
        #pragma unroll
        for (int nt = 0; nt < 8; nt++)
            #pragma unroll
            for (int q = 0; q < 4; q++) acc[mt][nt][q] = 0.f;

    for (int c = 0; c < NC1; c++) {
        int s = c & (NSTG - 1);
        MBAR_WAIT(sb + OFF_MBAR + s * 8, (c >> 2) & 1);
        uint32_t bA = sb + s * STG1, bB = bA + A_TS;
        bool dolo = ((c & 1) == 0);
        #pragma unroll
        for (int ks = 0; ks < 2; ks++) {
            uint32_t ah[4][4], bh[8][2], bl[8][2];
            #pragma unroll
            for (int mt = 0; mt < 4; mt++)
                ldsm4t(ah[mt][0], ah[mt][1], ah[mt][2], ah[mt][3], bA + aoff[ks][mt]);
            #pragma unroll
            for (int p = 0; p < 4; p++)
                ldsm4(bh[2*p][0], bh[2*p][1], bh[2*p+1][0], bh[2*p+1][1], bB + bho[ks][p]);
            if (dolo) {
                #pragma unroll
                for (int p = 0; p < 4; p++)
                    ldsm4(bl[2*p][0], bl[2*p][1], bl[2*p+1][0], bl[2*p+1][1],
                          bB + BH_TS + bho[ks][p]);
            }
            #pragma unroll
            for (int mt = 0; mt < 4; mt++)
                #pragma unroll
                for (int nt = 0; nt < 8; nt++) {
                    mma_h(acc[mt][nt], ah[mt], bh[nt]);
                    if (dolo) mma_h(acc[mt][nt], ah[mt], bl[nt]);
                }
        }
        __syncthreads();
        if (tid == 0 && c + NSTG < NC1) {
            int cn = c + NSTG;
            uint32_t mb = sb + OFF_MBAR + s * 8;
            uint32_t bby = (cn & 1) ? BH_TS : 2 * BH_TS;
            MBAR_EXPECT_TX(mb, A_TS + bby);
            bulk_g2s(sb + s * STG1, phiB + (size_t)cn * A_TS, A_TS, mb);
            bulk_g2s(sb + s * STG1 + A_TS, w1p + (size_t)cn * (4 * BH_TS), bby, mb);
        }
    }

    // ---- epilogue: relu+bias -> smem [n][m] -> packed h1 blocks -------------
    int g = lane >> 2, t = lane & 3;
    __half* se = (__half*)smem;
    #pragma unroll
    for (int mt = 0; mt < 4; mt++) {
        int ml = wm + mt * 16 + g;
        #pragma unroll
        for (int nt = 0; nt < 8; nt++) {
            int ncl = wn + nt * 8 + 2 * t;
            #pragma unroll
            for (int h = 0; h < 2; h++) {
                int mrow = ml + h * 8;
                float v0 = fmaxf(acc[mt][nt][2 * h]     + s_bias[ncl], 0.f);
                float v1 = fmaxf(acc[mt][nt][2 * h + 1] + s_bias[ncl + 1], 0.f);
                se[(size_t)ncl * (RS_E / 2) + mrow]       = __float2half_rn(v0);
                se[(size_t)(ncl + 1) * (RS_E / 2) + mrow] = __float2half_rn(v1);
            }
        }
    }
    __syncthreads();
    size_t h1base = ((size_t)mtile * NC2 + (size_t)nb * 8) * A_TS;
    #pragma unroll
    for (int i = tid; i < 4096; i += 256) {
        int cc = i >> 9, rem = i & 511, k = rem >> 4, u = rem & 15;
        uint32_t saddr = sb + (uint32_t)((cc * 32 + k) * RS_E + u * 16);
        uint32_t r0, r1, r2, r3;
        asm volatile("ld.shared.v4.b32 {%0,%1,%2,%3},[%4];"
            : "=r"(r0), "=r"(r1), "=r"(r2), "=r"(r3) : "r"(saddr));
        *(uint4*)(g_h1B + h1base + (size_t)cc * A_TS + k * 256 + ((u ^ (k & 7)) << 4))
            = make_uint4(r0, r1, r2, r3);
    }
}

// -------------------- GEMM2: bulk ring, C[128m, 96n] --------------------------
__global__ void __launch_bounds__(256, 1) k_gemm2(float* __restrict__ dout) {
    constexpr int OFF_BIAS = NSTG * STG2;          // 81920
    constexpr int OFF_MBAR = OFF_BIAS + 512;
    extern __shared__ char smem[];
    uint32_t sb = smem_u32(smem);
    float* s_bias = (float*)(smem + OFF_BIAS);
    int tid = threadIdx.x, wid = tid >> 5, lane = tid & 31;
    int grp = lane >> 3, rr = lane & 7;
    int wm = (wid & 3) * 32, wn = (wid >> 2) * 48;
    int mtile = blockIdx.x;
    int m0 = mtile * 128;

    if (tid == 0) {
        #pragma unroll
        for (int s = 0; s < NSTG; s++) MBAR_INIT(sb + OFF_MBAR + s * 8, 1);
        asm volatile("fence.proxy.async.shared::cta;" ::: "memory");
    }
    for (int i = tid; i < 96; i += 256) s_bias[i] = g_b2f[i];
    __syncthreads();

    const uint8_t* aB = g_h1B + (size_t)mtile * ((size_t)NC2 * A_TS);

    if (tid == 0) {
        #pragma unroll
        for (int s = 0; s < NSTG; s++) {
            uint32_t mb = sb + OFF_MBAR + s * 8;
            MBAR_EXPECT_TX(mb, STG2);
            bulk_g2s(sb + s * STG2, aB + (size_t)s * A_TS, A_TS, mb);
            bulk_g2s(sb + s * STG2 + A_TS, g_W2p + (size_t)s * B2_TS, B2_TS, mb);
        }
    }

    uint32_t aoff[2][2], bho[2][3], blo[2][3];
    #pragma unroll
    for (int ks = 0; ks < 2; ks++) {
        #pragma unroll
        for (int mt = 0; mt < 2; mt++) {
            int row = ks * 16 + (grp >> 1) * 8 + rr;
            int u = (wm >> 3) + mt * 2 + (grp & 1);
            aoff[ks][mt] = (uint32_t)(row * 256 + ((u ^ rr) << 4));
        }
        #pragma unroll
        for (int p = 0; p < 3; p++) {
            int n = wn + p * 16 + (grp >> 1) * 8 + rr;
            int uh = ks * 2 + (grp & 1);
            bho[ks][p] = (uint32_t)(n * 128 + ((uh ^ (n & 7)) << 4));
            blo[ks][p] = (uint32_t)(n * 128 + (((uh + 4) ^ (n & 7)) << 4));
        }
    }

    float acc[2][6][4];
    #pragma unroll
    for (int mt = 0; mt < 2; mt++)
        #pragma unroll
        for (int nt = 0; nt < 6; nt++)
            #pragma unroll
            for (int q = 0; q < 4; q++) acc[mt][nt][q] = 0.f;

    for (int c = 0; c < NC2; c++) {
        int s = c & (NSTG - 1);
        MBAR_WAIT(sb + OFF_MBAR + s * 8, (c >> 2) & 1);
        uint32_t bA = sb + s * STG2, bB = bA + A_TS;
        #pragma unroll
        for (int ks = 0; ks < 2; ks++) {
            uint32_t ah[2][4], bh[6][2], bl[6][2];
            #pragma unroll
            for (int mt = 0; mt < 2; mt++)
                ldsm4t(ah[mt][0], ah[mt][1], ah[mt][2], ah[mt][3], bA + aoff[ks][mt]);
            #pragma unroll
            for (int p = 0; p < 3; p++) {
                ldsm4(bh[2*p][0], bh[2*p][1], bh[2*p+1][0], bh[2*p+1][1], bB + bho[ks][p]);
                ldsm4(bl[2*p][0], bl[2*p][1], bl[2*p+1][0], bl[2*p+1][1], bB + blo[ks][p]);
            }
            #pragma unroll
            for (int mt = 0; mt < 2; mt++)
                #pragma unroll
                for (int nt = 0; nt < 6; nt++) {
                    mma_h(acc[mt][nt], ah[mt], bh[nt]);
                    mma_h(acc[mt][nt], ah[mt], bl[nt]);
                }
        }
        __syncthreads();
        if (tid == 0 && c + NSTG < NC2) {
            uint32_t mb = sb + OFF_MBAR + s * 8;
            MBAR_EXPECT_TX(mb, STG2);
            bulk_g2s(sb + s * STG2, aB + (size_t)(c + NSTG) * A_TS, A_TS, mb);
            bulk_g2s(sb + s * STG2 + A_TS, g_W2p + (size_t)(c + NSTG) * B2_TS, B2_TS, mb);
        }
    }

    int g = lane >> 2, t = lane & 3;
    #pragma unroll
    for (int mt = 0; mt < 2; mt++) {
        int mr = m0 + wm + mt * 16 + g;
        #pragma unroll
        for (int nt = 0; nt < 6; nt++) {
            int nc = wn + nt * 8 + 2 * t;
            #pragma unroll
            for (int h = 0; h < 2; h++) {
                int mrow = mr + h * 8;
                int b = mrow >> 14, pix = mrow & (HWn - 1);
                dout[(size_t)(b * N2 + nc) * HWn + pix]     = acc[mt][nt][2 * h]     + s_bias[nc];
                dout[(size_t)(b * N2 + nc + 1) * HWn + pix] = acc[mt][nt][2 * h + 1] + s_bias[nc + 1];
            }
        }
    }
}

// -------------------- launch ------------------------------------------------
extern "C" void kernel_launch(void* const* d_in, const int* in_sizes, int n_in,
                              void* d_out, int out_size) {
    (void)in_sizes; (void)n_in; (void)out_size;
    const float* x   = (const float*)d_in[0];
    const float* g1  = (const float*)d_in[1];
    const float* be1 = (const float*)d_in[2];
    const float* mu1 = (const float*)d_in[3];
    const float* va1 = (const float*)d_in[4];
    const float* W1  = (const float*)d_in[5];
    const float* b1  = (const float*)d_in[6];
    const float* g2  = (const float*)d_in[7];
    const float* be2 = (const float*)d_in[8];
    const float* mu2 = (const float*)d_in[9];
    const float* va2 = (const float*)d_in[10];
    const float* W2  = (const float*)d_in[11];
    const float* b2  = (const float*)d_in[12];

    constexpr int S1 = NSTG * STG1 + 1024 + NSTG * 8 + 32;   // ~165 KB
    constexpr int S2 = NSTG * STG2 + 512 + NSTG * 8 + 32;    // ~82.5 KB
    cudaFuncSetAttribute(k_gemm1, cudaFuncAttributeMaxDynamicSharedMemorySize, S1);
    cudaFuncSetAttribute(k_gemm2, cudaFuncAttributeMaxDynamicSharedMemorySize, S2);

    int satBlks = (NSAT + 255) / 256;
    k_pre<<<PRE_FOLD_BLKS + satBlks, 256>>>(x, W1, b1, g1, be1, mu1, va1,
                                            W2, b2, g2, be2, mu2, va2);
    k_sat_cols<<<(NSAT + 127) / 128, 128>>>();
    k_features<<<dim3(Mtot / 512, 13), 256>>>(x);

    k_gemm1<<<dim3(2, Mtot / 128), 256, S1>>>();
    k_gemm2<<<dim3(Mtot / 128, 1), 256, S2>>>((float*)d_out);
}

// round 10
// speedup vs baseline: 1.0287x; 1.0287x over previous
#include <cuda_runtime.h>
#include <cuda_fp16.h>
#include <cstdint>

// ---------------------------------------------------------------------------
// RingNet: SAT box features -> folded GEMM1 -> ReLU -> folded GEMM2.
// A single fp16, B hi+lo fp16 (lo-correction on every 3rd K-chunk; other
// chunks neither stage nor multiply the lo block). Operands pre-packed into
// chunk-contiguous XOR-swizzled blocks, staged by cp.async.bulk rings.
// ---------------------------------------------------------------------------

namespace {
constexpr int Bn = 4, Cn = 96, Hn = 128, Wn = 128;
constexpr int HWn = Hn * Wn;           // 16384
constexpr int Mtot = Bn * HWn;         // 65536
constexpr int K1 = 1248, N1 = 512, N2 = 96;
constexpr int NC1 = K1 / 32;           // 39
constexpr int NC2 = N1 / 32;           // 16
constexpr int SATR = 129, SATC = 132;
constexpr float BN_EPS = 1e-5f;
constexpr int A_TS = 8192;             // 32k x 256B (128 m)
constexpr int BH_TS = 16384;           // 256n x 64B (hi OR lo block)
constexpr int STG1 = A_TS + 2 * BH_TS; // 40960
constexpr int B2_TS = 12288;           // 96n x 128B hi|lo (GEMM2)
constexpr int STG2 = A_TS + B2_TS;     // 20480
constexpr int NSTG = 4;
constexpr int NSAT = Bn * Cn * SATR;   // 49536
}

// -------------------- device scratch ----------------------------------------
__device__ float   g_sat[(size_t)Bn * Cn * SATR * SATC];            // 26 MB
__device__ uint8_t g_phiB[(size_t)(Mtot / 128) * NC1 * A_TS];       // 164 MB
__device__ uint8_t g_W1p[(size_t)NC1 * 2 * 2 * BH_TS];              // 2.5 MB
__device__ uint8_t g_h1B[(size_t)(Mtot / 128) * NC2 * A_TS];        // 67 MB
__device__ uint8_t g_W2p[(size_t)NC2 * B2_TS];                      // 196 KB
__device__ float   g_b1f[N1], g_b2f[N2];

// -------------------- helpers ------------------------------------------------
__device__ __forceinline__ uint32_t smem_u32(const void* p) {
    uint32_t a;
    asm("{ .reg .u64 t; cvta.to.shared.u64 t, %1; cvt.u32.u64 %0, t; }" : "=r"(a) : "l"(p));
    return a;
}
__device__ __forceinline__ void bulk_g2s(uint32_t dst, const void* src, uint32_t bytes,
                                         uint32_t mbar) {
    asm volatile(
        "cp.async.bulk.shared::cluster.global.mbarrier::complete_tx::bytes [%0], [%1], %2, [%3];"
        :: "r"(dst), "l"(src), "r"(bytes), "r"(mbar) : "memory");
}
#define MBAR_INIT(a, n) \
    asm volatile("mbarrier.init.shared.b64 [%0], %1;" :: "r"(a), "r"((uint32_t)(n)) : "memory")
#define MBAR_EXPECT_TX(a, n) \
    asm volatile("mbarrier.arrive.expect_tx.shared.b64 _, [%0], %1;" \
        :: "r"(a), "r"((uint32_t)(n)) : "memory")
#define MBAR_WAIT(a, p) do { \
    uint32_t _m = (a), _p = (uint32_t)(p), _d; \
    asm volatile("{\n\t.reg .pred q;\n\t" \
        "mbarrier.try_wait.parity.acquire.cta.shared::cta.b64 q, [%1], %2;\n\t" \
        "selp.b32 %0, 1, 0, q;\n\t}" : "=r"(_d) : "r"(_m), "r"(_p) : "memory"); \
    if (!_d) { \
        asm volatile("{\n\t.reg .pred Q;\n\tWL_%=:\n\t" \
            "mbarrier.try_wait.parity.acquire.cta.shared::cta.b64 Q, [%0], %1, 0x989680;\n\t" \
            "@Q bra.uni WD_%=;\n\tbra.uni WL_%=;\n\tWD_%=:\n\t}" \
            :: "r"(_m), "r"(_p) : "memory"); \
    } } while (0)
__device__ __forceinline__ void mma_h(float* c, const uint32_t* a, const uint32_t* b) {
    asm volatile(
        "mma.sync.aligned.m16n8k16.row.col.f32.f16.f16.f32 "
        "{%0,%1,%2,%3},{%4,%5,%6,%7},{%8,%9},{%0,%1,%2,%3};\n"
        : "+f"(c[0]), "+f"(c[1]), "+f"(c[2]), "+f"(c[3])
        : "r"(a[0]), "r"(a[1]), "r"(a[2]), "r"(a[3]), "r"(b[0]), "r"(b[1]));
}
__device__ __forceinline__ void ldsm4(uint32_t& a, uint32_t& b, uint32_t& c, uint32_t& d,
                                      uint32_t addr) {
    asm volatile("ldmatrix.sync.aligned.m8n8.x4.shared.b16 {%0,%1,%2,%3},[%4];"
        : "=r"(a), "=r"(b), "=r"(c), "=r"(d) : "r"(addr));
}
__device__ __forceinline__ void ldsm4t(uint32_t& a, uint32_t& b, uint32_t& c, uint32_t& d,
                                       uint32_t addr) {
    asm volatile("ldmatrix.sync.aligned.m8n8.x4.trans.shared.b16 {%0,%1,%2,%3},[%4];"
        : "=r"(a), "=r"(b), "=r"(c), "=r"(d) : "r"(addr));
}

// -------------------- weight folding + packing (separate launch) -------------
__global__ void k_folds(const float* __restrict__ W1, const float* __restrict__ b1,
                        const float* __restrict__ ga1, const float* __restrict__ be1,
                        const float* __restrict__ mu1, const float* __restrict__ va1,
                        const float* __restrict__ W2, const float* __restrict__ b2,
                        const float* __restrict__ ga2, const float* __restrict__ be2,
                        const float* __restrict__ mu2, const float* __restrict__ va2) {
    int tid = threadIdx.x;
    float part = 0.f;
    if (blockIdx.x < N1) {
        int o = blockIdx.x;
        int nb = o >> 8, nlo = o & 255;
        int swz = (nlo >> 1) & 3;
        for (int k = tid; k < K1; k += 256) {
            float s = ga1[k] * rsqrtf(va1[k] + BN_EPS);
            float w = W1[(size_t)o * K1 + k];
            part += w * (be1[k] - mu1[k] * s);
            float wb = w * s;
            if (k < K1 - 96) {
                float s2 = ga1[k + 96] * rsqrtf(va1[k + 96] + BN_EPS);
                wb -= W1[(size_t)o * K1 + k + 96] * s2;
            }
            __half hi = __float2half_rn(wb);
            __half lo = __float2half_rn(wb - __half2float(hi));
            int ck = k >> 5, u = (k >> 3) & 3, byo = (k & 7) * 2;
            // layout: [ck][nb][hi 16KB][lo 16KB], 64B rows
            size_t base = (size_t)ck * (4 * BH_TS) + (size_t)nb * (2 * BH_TS)
                        + (size_t)nlo * 64 + (size_t)((u ^ swz) << 4) + byo;
            *(__half*)(g_W1p + base) = hi;
            *(__half*)(g_W1p + base + BH_TS) = lo;
        }
    } else {
        int o = blockIdx.x - N1;       // 0..95
        int nsw = o & 7;
        for (int k = tid; k < N1; k += 256) {
            float s = ga2[k] * rsqrtf(va2[k] + BN_EPS);
            float w = W2[(size_t)o * N1 + k];
            part += w * (be2[k] - mu2[k] * s);
            float wf = w * s;
            __half hi = __float2half_rn(wf);
            __half lo = __float2half_rn(wf - __half2float(hi));
            int ck = k >> 5, uh = (k >> 3) & 3, byo = (k & 7) * 2;
            size_t base = (size_t)ck * B2_TS + (size_t)o * 128;
            *(__half*)(g_W2p + base + ((uh ^ nsw) << 4) + byo) = hi;
            *(__half*)(g_W2p + base + (((uh + 4) ^ nsw) << 4) + byo) = lo;
        }
    }
    __shared__ float red[256];
    red[tid] = part; __syncthreads();
    for (int s = 128; s > 0; s >>= 1) { if (tid < s) red[tid] += red[tid + s]; __syncthreads(); }
    if (tid == 0) {
        if (blockIdx.x < N1) g_b1f[blockIdx.x] = b1[blockIdx.x] + red[0];
        else g_b2f[blockIdx.x - N1] = b2[blockIdx.x - N1] + red[0];
    }
}

// -------------------- summed-area tables --------------------------------------
__global__ void k_sat_rows(const float* __restrict__ x) {
    int idx = blockIdx.x * blockDim.x + threadIdx.x;
    if (idx >= NSAT) return;
    int img = idx / SATR, r = idx % SATR;
    float* S = g_sat + (size_t)img * SATR * SATC;
    if (r == 0) { for (int cx = 0; cx <= 128; cx++) S[cx] = 0.f; }
    else {
        const float* row = x + (size_t)img * HWn + (size_t)(r - 1) * Wn;
        float* Sr = S + (size_t)r * SATC;
        Sr[0] = 0.f;
        float acc = 0.f;
        for (int xx = 0; xx < Wn; xx++) { acc += row[xx]; Sr[xx + 1] = acc; }
    }
}
__global__ void k_sat_cols() {
    int idx = blockIdx.x * blockDim.x + threadIdx.x;
    if (idx >= NSAT) return;
    int img = idx / SATR, cc = idx % SATR;
    float* S = g_sat + (size_t)img * SATR * SATC;
    float acc = 0.f;
    for (int r = 1; r <= 128; r++) {
        acc += S[(size_t)r * SATC + cc];
        S[(size_t)r * SATC + cc] = acc;
    }
}

// -------------------- features (R6 2-pixel version) ---------------------------
__global__ void k_features(const float* __restrict__ x) {
    int j = blockIdx.y;                           // 0..12
    int m = blockIdx.x * 512 + threadIdx.x * 2;
    int b = m >> 14, pix = m & (HWn - 1), y = pix >> 7, xx = pix & 127;
    int mtile = m >> 7, mloc = m & 127;
    uint32_t ub = (uint32_t)(mloc >> 3);
    size_t outm = (size_t)mtile * ((size_t)NC1 * A_TS) + (size_t)(mloc & 7) * 2;

    if (j == 0) {
        const float* p = x + (size_t)b * Cn * HWn + pix;
        #pragma unroll 4
        for (int c = 0; c < 96; c++) {
            float v0 = p[(size_t)c * HWn], v1 = p[(size_t)c * HWn + 1];
            size_t off = outm + (size_t)(c >> 5) * A_TS + (size_t)(c & 31) * 256
                       + (size_t)((ub ^ (uint32_t)(c & 7)) << 4);
            *(__half2*)(g_phiB + off) = __floats2half2_rn(v0, v1);
        }
    } else {
        int rlo = max(y - j, 0), rhi = min(y + j + 1, 128);
        int cl0 = max(xx - j, 0), ch0 = min(xx + j + 1, 128);
        int cl1 = max(xx + 1 - j, 0), ch1 = min(xx + j + 2, 128);
        int ohh0 = rhi * SATC + ch0, olh0 = rlo * SATC + ch0;
        int ohl0 = rhi * SATC + cl0, oll0 = rlo * SATC + cl0;
        int ohh1 = rhi * SATC + ch1, olh1 = rlo * SATC + ch1;
        int ohl1 = rhi * SATC + cl1, oll1 = rlo * SATC + cl1;
        const float* Sb = g_sat + (size_t)b * Cn * (SATR * SATC);
        #pragma unroll 2
        for (int c = 0; c < 96; c++) {
            const float* S = Sb + (size_t)c * (SATR * SATC);
            float v0 = S[ohh0] - S[olh0] - S[ohl0] + S[oll0];
            float v1 = S[ohh1] - S[olh1] - S[ohl1] + S[oll1];
            int k = j * 96 + c;
            size_t off = outm + (size_t)(k >> 5) * A_TS + (size_t)(k & 31) * 256
                       + (size_t)((ub ^ (uint32_t)(k & 7)) << 4);
            *(__half2*)(g_phiB + off) = __floats2half2_rn(v0, v1);
        }
    }
}

// -------------------- GEMM1: bulk ring; B-lo on every 3rd chunk ---------------
// C[128m, 256n] per CTA, 8 warps (2m x 4n). Epilogue: smem transpose ->
// packed h1 blocks (same format as phi).
__global__ void __launch_bounds__(256, 1) k_gemm1() {
    constexpr int OFF_BIAS = NSTG * STG1;          // 163840
    constexpr int OFF_MBAR = OFF_BIAS + 1024;
    constexpr int RS_E = 272;                      // epilogue row stride
    extern __shared__ char smem[];
    uint32_t sb = smem_u32(smem);
    float* s_bias = (float*)(smem + OFF_BIAS);
    int tid = threadIdx.x, wid = tid >> 5, lane = tid & 31;
    int grp = lane >> 3, rr = lane & 7;
    int wm = (wid & 1) * 64, wn = (wid >> 1) * 64;
    int nb = blockIdx.x, mtile = blockIdx.y;       // x fast -> L2 phi pairing
    int n0 = nb * 256;

    if (tid == 0) {
        #pragma unroll
        for (int s = 0; s < NSTG; s++) MBAR_INIT(sb + OFF_MBAR + s * 8, 1);
        asm volatile("fence.proxy.async.shared::cta;" ::: "memory");
    }
    for (int i = tid; i < 256; i += 256) s_bias[i] = g_b1f[n0 + i];
    __syncthreads();

    const uint8_t* phiB = g_phiB + (size_t)mtile * ((size_t)NC1 * A_TS);
    const uint8_t* w1p  = g_W1p + (size_t)nb * (2 * BH_TS);

    if (tid == 0) {
        #pragma unroll
        for (int s = 0; s < NSTG; s++) {
            uint32_t mb = sb + OFF_MBAR + s * 8;
            uint32_t bby = (s % 3 == 0) ? 2 * BH_TS : BH_TS;   // lo every 3rd
            MBAR_EXPECT_TX(mb, A_TS + bby);
            bulk_g2s(sb + s * STG1, phiB + (size_t)s * A_TS, A_TS, mb);
            bulk_g2s(sb + s * STG1 + A_TS, w1p + (size_t)s * (4 * BH_TS), bby, mb);
        }
    }

    uint32_t aoff[2][4], bho[2][4];
    #pragma unroll
    for (int ks = 0; ks < 2; ks++) {
        #pragma unroll
        for (int mt = 0; mt < 4; mt++) {
            int row = ks * 16 + (grp >> 1) * 8 + rr;
            int u = (wm >> 3) + mt * 2 + (grp & 1);
            aoff[ks][mt] = (uint32_t)(row * 256 + ((u ^ rr) << 4));
        }
        #pragma unroll
        for (int p = 0; p < 4; p++) {
            int n = wn + p * 16 + (grp >> 1) * 8 + rr;
            int uh = ks * 2 + (grp & 1);
            bho[ks][p] = (uint32_t)(n * 64 + ((uh ^ ((n >> 1) & 3)) << 4));
        }
    }

    float acc[4][8][4];
    #pragma unroll
    for (int mt = 0; mt < 4; mt++)
        #pragma unroll
        for (int nt = 0; nt < 8; nt++)
            #pragma unroll
            for (int q = 0; q < 4; q++) acc[mt][nt][q] = 0.f;

    for (int c = 0; c < NC1; c++) {
        int s = c & (NSTG - 1);
        MBAR_WAIT(sb + OFF_MBAR + s * 8, (c >> 2) & 1);
        uint32_t bA = sb + s * STG1, bB = bA + A_TS;
        bool dolo = (c % 3 == 0);
        #pragma unroll
        for (int ks = 0; ks < 2; ks++) {
            uint32_t ah[4][4], bh[8][2], bl[8][2];
            #pragma unroll
            for (int mt = 0; mt < 4; mt++)
                ldsm4t(ah[mt][0], ah[mt][1], ah[mt][2], ah[mt][3], bA + aoff[ks][mt]);
            #pragma unroll
            for (int p = 0; p < 4; p++)
                ldsm4(bh[2*p][0], bh[2*p][1], bh[2*p+1][0], bh[2*p+1][1], bB + bho[ks][p]);
            if (dolo) {
                #pragma unroll
                for (int p = 0; p < 4; p++)
                    ldsm4(bl[2*p][0], bl[2*p][1], bl[2*p+1][0], bl[2*p+1][1],
                          bB + BH_TS + bho[ks][p]);
            }
            #pragma unroll
            for (int mt = 0; mt < 4; mt++)
                #pragma unroll
                for (int nt = 0; nt < 8; nt++) {
                    mma_h(acc[mt][nt], ah[mt], bh[nt]);
                    if (dolo) mma_h(acc[mt][nt], ah[mt], bl[nt]);
                }
        }
        __syncthreads();
        if (tid == 0 && c + NSTG < NC1) {
            int cn = c + NSTG;
            uint32_t mb = sb + OFF_MBAR + s * 8;
            uint32_t bby = (cn % 3 == 0) ? 2 * BH_TS : BH_TS;
            MBAR_EXPECT_TX(mb, A_TS + bby);
            bulk_g2s(sb + s * STG1, phiB + (size_t)cn * A_TS, A_TS, mb);
            bulk_g2s(sb + s * STG1 + A_TS, w1p + (size_t)cn * (4 * BH_TS), bby, mb);
        }
    }

    // ---- epilogue: relu+bias -> smem [n][m] -> packed h1 blocks -------------
    int g = lane >> 2, t = lane & 3;
    __half* se = (__half*)smem;
    #pragma unroll
    for (int mt = 0; mt < 4; mt++) {
        int ml = wm + mt * 16 + g;
        #pragma unroll
        for (int nt = 0; nt < 8; nt++) {
            int ncl = wn + nt * 8 + 2 * t;
            #pragma unroll
            for (int h = 0; h < 2; h++) {
                int mrow = ml + h * 8;
                float v0 = fmaxf(acc[mt][nt][2 * h]     + s_bias[ncl], 0.f);
                float v1 = fmaxf(acc[mt][nt][2 * h + 1] + s_bias[ncl + 1], 0.f);
                se[(size_t)ncl * (RS_E / 2) + mrow]       = __float2half_rn(v0);
                se[(size_t)(ncl + 1) * (RS_E / 2) + mrow] = __float2half_rn(v1);
            }
        }
    }
    __syncthreads();
    size_t h1base = ((size_t)mtile * NC2 + (size_t)nb * 8) * A_TS;
    #pragma unroll
    for (int i = tid; i < 4096; i += 256) {
        int cc = i >> 9, rem = i & 511, k = rem >> 4, u = rem & 15;
        uint32_t saddr = sb + (uint32_t)((cc * 32 + k) * RS_E + u * 16);
        uint32_t r0, r1, r2, r3;
        asm volatile("ld.shared.v4.b32 {%0,%1,%2,%3},[%4];"
            : "=r"(r0), "=r"(r1), "=r"(r2), "=r"(r3) : "r"(saddr));
        *(uint4*)(g_h1B + h1base + (size_t)cc * A_TS + k * 256 + ((u ^ (k & 7)) << 4))
            = make_uint4(r0, r1, r2, r3);
    }
}

// -------------------- GEMM2: bulk ring, C[128m, 96n] --------------------------
__global__ void __launch_bounds__(256, 1) k_gemm2(float* __restrict__ dout) {
    constexpr int OFF_BIAS = NSTG * STG2;          // 81920
    constexpr int OFF_MBAR = OFF_BIAS + 512;
    extern __shared__ char smem[];
    uint32_t sb = smem_u32(smem);
    float* s_bias = (float*)(smem + OFF_BIAS);
    int tid = threadIdx.x, wid = tid >> 5, lane = tid & 31;
    int grp = lane >> 3, rr = lane & 7;
    int wm = (wid & 3) * 32, wn = (wid >> 2) * 48;
    int mtile = blockIdx.x;
    int m0 = mtile * 128;

    if (tid == 0) {
        #pragma unroll
        for (int s = 0; s < NSTG; s++) MBAR_INIT(sb + OFF_MBAR + s * 8, 1);
        asm volatile("fence.proxy.async.shared::cta;" ::: "memory");
    }
    for (int i = tid; i < 96; i += 256) s_bias[i] = g_b2f[i];
    __syncthreads();

    const uint8_t* aB = g_h1B + (size_t)mtile * ((size_t)NC2 * A_TS);

    if (tid == 0) {
        #pragma unroll
        for (int s = 0; s < NSTG; s++) {
            uint32_t mb = sb + OFF_MBAR + s * 8;
            MBAR_EXPECT_TX(mb, STG2);
            bulk_g2s(sb + s * STG2, aB + (size_t)s * A_TS, A_TS, mb);
            bulk_g2s(sb + s * STG2 + A_TS, g_W2p + (size_t)s * B2_TS, B2_TS, mb);
        }
    }

    uint32_t aoff[2][2], bho[2][3], blo[2][3];
    #pragma unroll
    for (int ks = 0; ks < 2; ks++) {
        #pragma unroll
        for (int mt = 0; mt < 2; mt++) {
            int row = ks * 16 + (grp >> 1) * 8 + rr;
            int u = (wm >> 3) + mt * 2 + (grp & 1);
            aoff[ks][mt] = (uint32_t)(row * 256 + ((u ^ rr) << 4));
        }
        #pragma unroll
        for (int p = 0; p < 3; p++) {
            int n = wn + p * 16 + (grp >> 1) * 8 + rr;
            int uh = ks * 2 + (grp & 1);
            bho[ks][p] = (uint32_t)(n * 128 + ((uh ^ (n & 7)) << 4));
            blo[ks][p] = (uint32_t)(n * 128 + (((uh + 4) ^ (n & 7)) << 4));
        }
    }

    float acc[2][6][4];
    #pragma unroll
    for (int mt = 0; mt < 2; mt++)
        #pragma unroll
        for (int nt = 0; nt < 6; nt++)
            #pragma unroll
            for (int q = 0; q < 4; q++) acc[mt][nt][q] = 0.f;

    for (int c = 0; c < NC2; c++) {
        int s = c & (NSTG - 1);
        MBAR_WAIT(sb + OFF_MBAR + s * 8, (c >> 2) & 1);
        uint32_t bA = sb + s * STG2, bB = bA + A_TS;
        #pragma unroll
        for (int ks = 0; ks < 2; ks++) {
            uint32_t ah[2][4], bh[6][2], bl[6][2];
            #pragma unroll
            for (int mt = 0; mt < 2; mt++)
                ldsm4t(ah[mt][0], ah[mt][1], ah[mt][2], ah[mt][3], bA + aoff[ks][mt]);
            #pragma unroll
            for (int p = 0; p < 3; p++) {
                ldsm4(bh[2*p][0], bh[2*p][1], bh[2*p+1][0], bh[2*p+1][1], bB + bho[ks][p]);
                ldsm4(bl[2*p][0], bl[2*p][1], bl[2*p+1][0], bl[2*p+1][1], bB + blo[ks][p]);
            }
            #pragma unroll
            for (int mt = 0; mt < 2; mt++)
                #pragma unroll
                for (int nt = 0; nt < 6; nt++) {
                    mma_h(acc[mt][nt], ah[mt], bh[nt]);
                    mma_h(acc[mt][nt], ah[mt], bl[nt]);
                }
        }
        __syncthreads();
        if (tid == 0 && c + NSTG < NC2) {
            uint32_t mb = sb + OFF_MBAR + s * 8;
            MBAR_EXPECT_TX(mb, STG2);
            bulk_g2s(sb + s * STG2, aB + (size_t)(c + NSTG) * A_TS, A_TS, mb);
            bulk_g2s(sb + s * STG2 + A_TS, g_W2p + (size_t)(c + NSTG) * B2_TS, B2_TS, mb);
        }
    }

    int g = lane >> 2, t = lane & 3;
    #pragma unroll
    for (int mt = 0; mt < 2; mt++) {
        int mr = m0 + wm + mt * 16 + g;
        #pragma unroll
        for (int nt = 0; nt < 6; nt++) {
            int nc = wn + nt * 8 + 2 * t;
            #pragma unroll
            for (int h = 0; h < 2; h++) {
                int mrow = mr + h * 8;
                int b = mrow >> 14, pix = mrow & (HWn - 1);
                dout[(size_t)(b * N2 + nc) * HWn + pix]     = acc[mt][nt][2 * h]     + s_bias[nc];
                dout[(size_t)(b * N2 + nc + 1) * HWn + pix] = acc[mt][nt][2 * h + 1] + s_bias[nc + 1];
            }
        }
    }
}

// -------------------- launch ------------------------------------------------
extern "C" void kernel_launch(void* const* d_in, const int* in_sizes, int n_in,
                              void* d_out, int out_size) {
    (void)in_sizes; (void)n_in; (void)out_size;
    const float* x   = (const float*)d_in[0];
    const float* g1  = (const float*)d_in[1];
    const float* be1 = (const float*)d_in[2];
    const float* mu1 = (const float*)d_in[3];
    const float* va1 = (const float*)d_in[4];
    const float* W1  = (const float*)d_in[5];
    const float* b1  = (const float*)d_in[6];
    const float* g2  = (const float*)d_in[7];
    const float* be2 = (const float*)d_in[8];
    const float* mu2 = (const float*)d_in[9];
    const float* va2 = (const float*)d_in[10];
    const float* W2  = (const float*)d_in[11];
    const float* b2  = (const float*)d_in[12];

    constexpr int S1 = NSTG * STG1 + 1024 + NSTG * 8 + 32;   // ~165 KB
    constexpr int S2 = NSTG * STG2 + 512 + NSTG * 8 + 32;    // ~82.5 KB
    cudaFuncSetAttribute(k_gemm1, cudaFuncAttributeMaxDynamicSharedMemorySize, S1);
    cudaFuncSetAttribute(k_gemm2, cudaFuncAttributeMaxDynamicSharedMemorySize, S2);

    k_folds<<<N1 + N2, 256>>>(W1, b1, g1, be1, mu1, va1, W2, b2, g2, be2, mu2, va2);
    k_sat_rows<<<(NSAT + 127) / 128, 128>>>(x);
    k_sat_cols<<<(NSAT + 127) / 128, 128>>>();
    k_features<<<dim3(Mtot / 512, 13), 256>>>(x);

    k_gemm1<<<dim3(2, Mtot / 128), 256, S1>>>();
    k_gemm2<<<dim3(Mtot / 128, 1), 256, S2>>>((float*)d_out);
}

// round 11
// speedup vs baseline: 1.0900x; 1.0596x over previous
#include <cuda_runtime.h>
#include <cuda_fp16.h>
#include <cstdint>

// ---------------------------------------------------------------------------
// RingNet: SAT box features -> folded GEMM1 -> ReLU -> folded GEMM2.
// A single fp16, B hi+lo fp16 (lo-correction applied on every 3rd K-chunk).
// All GEMM operands pre-packed into chunk-contiguous XOR-swizzled blocks
// staged by cp.async.bulk into 4-stage mbarrier rings.  (R8 baseline + f=1/3)
// ---------------------------------------------------------------------------

namespace {
constexpr int Bn = 4, Cn = 96, Hn = 128, Wn = 128;
constexpr int HWn = Hn * Wn;           // 16384
constexpr int Mtot = Bn * HWn;         // 65536
constexpr int K1 = 1248, N1 = 512, N2 = 96;
constexpr int NC1 = K1 / 32;           // 39
constexpr int NC2 = N1 / 32;           // 16
constexpr int SATR = 129, SATC = 132;
constexpr float BN_EPS = 1e-5f;
constexpr int A_TS = 8192;             // 32k x 256B (128 m)
constexpr int B_TS = 32768;            // 256n x 128B hi|lo
constexpr int STG1 = A_TS + B_TS;      // 40960
constexpr int B2_TS = 12288;           // 96n x 128B hi|lo
constexpr int STG2 = A_TS + B2_TS;     // 20480
constexpr int NSTG = 4;
}

// -------------------- device scratch ----------------------------------------
__device__ float   g_sat[(size_t)Bn * Cn * SATR * SATC];            // 26 MB
__device__ uint8_t g_phiB[(size_t)(Mtot / 128) * NC1 * A_TS];       // 164 MB
__device__ uint8_t g_W1p[(size_t)NC1 * 2 * B_TS];                   // 2.5 MB
__device__ uint8_t g_h1B[(size_t)(Mtot / 128) * NC2 * A_TS];        // 67 MB
__device__ uint8_t g_W2p[(size_t)NC2 * B2_TS];                      // 196 KB
__device__ float   g_b1f[N1], g_b2f[N2];

// -------------------- helpers ------------------------------------------------
__device__ __forceinline__ uint32_t smem_u32(const void* p) {
    uint32_t a;
    asm("{ .reg .u64 t; cvta.to.shared.u64 t, %1; cvt.u32.u64 %0, t; }" : "=r"(a) : "l"(p));
    return a;
}
__device__ __forceinline__ void bulk_g2s(uint32_t dst, const void* src, uint32_t bytes,
                                         uint32_t mbar) {
    asm volatile(
        "cp.async.bulk.shared::cluster.global.mbarrier::complete_tx::bytes [%0], [%1], %2, [%3];"
        :: "r"(dst), "l"(src), "r"(bytes), "r"(mbar) : "memory");
}
#define MBAR_INIT(a, n) \
    asm volatile("mbarrier.init.shared.b64 [%0], %1;" :: "r"(a), "r"((uint32_t)(n)) : "memory")
#define MBAR_EXPECT_TX(a, n) \
    asm volatile("mbarrier.arrive.expect_tx.shared.b64 _, [%0], %1;" \
        :: "r"(a), "r"((uint32_t)(n)) : "memory")
#define MBAR_WAIT(a, p) do { \
    uint32_t _m = (a), _p = (uint32_t)(p), _d; \
    asm volatile("{\n\t.reg .pred q;\n\t" \
        "mbarrier.try_wait.parity.acquire.cta.shared::cta.b64 q, [%1], %2;\n\t" \
        "selp.b32 %0, 1, 0, q;\n\t}" : "=r"(_d) : "r"(_m), "r"(_p) : "memory"); \
    if (!_d) { \
        asm volatile("{\n\t.reg .pred Q;\n\tWL_%=:\n\t" \
            "mbarrier.try_wait.parity.acquire.cta.shared::cta.b64 Q, [%0], %1, 0x989680;\n\t" \
            "@Q bra.uni WD_%=;\n\tbra.uni WL_%=;\n\tWD_%=:\n\t}" \
            :: "r"(_m), "r"(_p) : "memory"); \
    } } while (0)
__device__ __forceinline__ void mma_h(float* c, const uint32_t* a, const uint32_t* b) {
    asm volatile(
        "mma.sync.aligned.m16n8k16.row.col.f32.f16.f16.f32 "
        "{%0,%1,%2,%3},{%4,%5,%6,%7},{%8,%9},{%0,%1,%2,%3};\n"
        : "+f"(c[0]), "+f"(c[1]), "+f"(c[2]), "+f"(c[3])
        : "r"(a[0]), "r"(a[1]), "r"(a[2]), "r"(a[3]), "r"(b[0]), "r"(b[1]));
}
__device__ __forceinline__ void ldsm4(uint32_t& a, uint32_t& b, uint32_t& c, uint32_t& d,
                                      uint32_t addr) {
    asm volatile("ldmatrix.sync.aligned.m8n8.x4.shared.b16 {%0,%1,%2,%3},[%4];"
        : "=r"(a), "=r"(b), "=r"(c), "=r"(d) : "r"(addr));
}
__device__ __forceinline__ void ldsm4t(uint32_t& a, uint32_t& b, uint32_t& c, uint32_t& d,
                                       uint32_t addr) {
    asm volatile("ldmatrix.sync.aligned.m8n8.x4.trans.shared.b16 {%0,%1,%2,%3},[%4];"
        : "=r"(a), "=r"(b), "=r"(c), "=r"(d) : "r"(addr));
}

// -------------------- weight folding + packing -------------------------------
__global__ void k_folds(const float* __restrict__ W1, const float* __restrict__ b1,
                        const float* __restrict__ ga1, const float* __restrict__ be1,
                        const float* __restrict__ mu1, const float* __restrict__ va1,
                        const float* __restrict__ W2, const float* __restrict__ b2,
                        const float* __restrict__ ga2, const float* __restrict__ be2,
                        const float* __restrict__ mu2, const float* __restrict__ va2) {
    int tid = threadIdx.x;
    float part = 0.f;
    if (blockIdx.x < N1) {
        int o = blockIdx.x;
        int nb = o >> 8, nlo = o & 255;
        size_t rowbase = (size_t)nb * B_TS + (size_t)nlo * 128;
        int nsw = nlo & 7;
        for (int k = tid; k < K1; k += 256) {
            float s = ga1[k] * rsqrtf(va1[k] + BN_EPS);
            float w = W1[(size_t)o * K1 + k];
            part += w * (be1[k] - mu1[k] * s);
            float wb = w * s;
            if (k < K1 - 96) {
                float s2 = ga1[k + 96] * rsqrtf(va1[k + 96] + BN_EPS);
                wb -= W1[(size_t)o * K1 + k + 96] * s2;
            }
            __half hi = __float2half_rn(wb);
            __half lo = __float2half_rn(wb - __half2float(hi));
            int ck = k >> 5, uh = (k >> 3) & 3, byo = (k & 7) * 2;
            size_t base = (size_t)ck * (2 * B_TS) + rowbase;
            *(__half*)(g_W1p + base + ((uh ^ nsw) << 4) + byo) = hi;
            *(__half*)(g_W1p + base + (((uh + 4) ^ nsw) << 4) + byo) = lo;
        }
    } else {
        int o = blockIdx.x - N1;       // 0..95
        int nsw = o & 7;
        for (int k = tid; k < N1; k += 256) {
            float s = ga2[k] * rsqrtf(va2[k] + BN_EPS);
            float w = W2[(size_t)o * N1 + k];
            part += w * (be2[k] - mu2[k] * s);
            float wf = w * s;
            __half hi = __float2half_rn(wf);
            __half lo = __float2half_rn(wf - __half2float(hi));
            int ck = k >> 5, uh = (k >> 3) & 3, byo = (k & 7) * 2;
            size_t base = (size_t)ck * B2_TS + (size_t)o * 128;
            *(__half*)(g_W2p + base + ((uh ^ nsw) << 4) + byo) = hi;
            *(__half*)(g_W2p + base + (((uh + 4) ^ nsw) << 4) + byo) = lo;
        }
    }
    __shared__ float red[256];
    red[tid] = part; __syncthreads();
    for (int s = 128; s > 0; s >>= 1) { if (tid < s) red[tid] += red[tid + s]; __syncthreads(); }
    if (tid == 0) {
        if (blockIdx.x < N1) g_b1f[blockIdx.x] = b1[blockIdx.x] + red[0];
        else g_b2f[blockIdx.x - N1] = b2[blockIdx.x - N1] + red[0];
    }
}

// -------------------- summed-area tables --------------------------------------
__global__ void k_sat_rows(const float* __restrict__ x) {
    int idx = blockIdx.x * blockDim.x + threadIdx.x;
    if (idx >= Bn * Cn * SATR) return;
    int img = idx / SATR, r = idx % SATR;
    float* S = g_sat + (size_t)img * SATR * SATC;
    if (r == 0) { for (int cx = 0; cx <= 128; cx++) S[cx] = 0.f; }
    else {
        const float* row = x + (size_t)img * HWn + (size_t)(r - 1) * Wn;
        float* Sr = S + (size_t)r * SATC;
        Sr[0] = 0.f;
        float acc = 0.f;
        for (int xx = 0; xx < Wn; xx++) { acc += row[xx]; Sr[xx + 1] = acc; }
    }
}
__global__ void k_sat_cols() {
    int idx = blockIdx.x * blockDim.x + threadIdx.x;
    if (idx >= Bn * Cn * SATR) return;
    int img = idx / SATR, cc = idx % SATR;
    float* S = g_sat + (size_t)img * SATR * SATC;
    float acc = 0.f;
    for (int r = 1; r <= 128; r++) {
        acc += S[(size_t)r * SATC + cc];
        S[(size_t)r * SATC + cc] = acc;
    }
}

// -------------------- features (R6 2-pixel version) ---------------------------
__global__ void k_features(const float* __restrict__ x) {
    int j = blockIdx.y;                           // 0..12
    int m = blockIdx.x * 512 + threadIdx.x * 2;
    int b = m >> 14, pix = m & (HWn - 1), y = pix >> 7, xx = pix & 127;
    int mtile = m >> 7, mloc = m & 127;
    uint32_t ub = (uint32_t)(mloc >> 3);
    size_t outm = (size_t)mtile * ((size_t)NC1 * A_TS) + (size_t)(mloc & 7) * 2;

    if (j == 0) {
        const float* p = x + (size_t)b * Cn * HWn + pix;
        #pragma unroll 4
        for (int c = 0; c < 96; c++) {
            float v0 = p[(size_t)c * HWn], v1 = p[(size_t)c * HWn + 1];
            size_t off = outm + (size_t)(c >> 5) * A_TS + (size_t)(c & 31) * 256
                       + (size_t)((ub ^ (uint32_t)(c & 7)) << 4);
            *(__half2*)(g_phiB + off) = __floats2half2_rn(v0, v1);
        }
    } else {
        int rlo = max(y - j, 0), rhi = min(y + j + 1, 128);
        int cl0 = max(xx - j, 0), ch0 = min(xx + j + 1, 128);
        int cl1 = max(xx + 1 - j, 0), ch1 = min(xx + j + 2, 128);
        int ohh0 = rhi * SATC + ch0, olh0 = rlo * SATC + ch0;
        int ohl0 = rhi * SATC + cl0, oll0 = rlo * SATC + cl0;
        int ohh1 = rhi * SATC + ch1, olh1 = rlo * SATC + ch1;
        int ohl1 = rhi * SATC + cl1, oll1 = rlo * SATC + cl1;
        const float* Sb = g_sat + (size_t)b * Cn * (SATR * SATC);
        #pragma unroll 2
        for (int c = 0; c < 96; c++) {
            const float* S = Sb + (size_t)c * (SATR * SATC);
            float v0 = S[ohh0] - S[olh0] - S[ohl0] + S[oll0];
            float v1 = S[ohh1] - S[olh1] - S[ohl1] + S[oll1];
            int k = j * 96 + c;
            size_t off = outm + (size_t)(k >> 5) * A_TS + (size_t)(k & 31) * 256
                       + (size_t)((ub ^ (uint32_t)(k & 7)) << 4);
            *(__half2*)(g_phiB + off) = __floats2half2_rn(v0, v1);
        }
    }
}

// -------------------- GEMM1: bulk ring, B-lo on every 3rd chunk ---------------
// C[128m, 256n] per CTA, 8 warps (2m x 4n). Epilogue: smem transpose ->
// packed h1 blocks (same format as phi).
__global__ void __launch_bounds__(256, 1) k_gemm1() {
    constexpr int OFF_BIAS = NSTG * STG1;          // 163840
    constexpr int OFF_MBAR = OFF_BIAS + 1024;
    constexpr int RS_E = 272;                      // epilogue row stride
    extern __shared__ char smem[];
    uint32_t sb = smem_u32(smem);
    float* s_bias = (float*)(smem + OFF_BIAS);
    int tid = threadIdx.x, wid = tid >> 5, lane = tid & 31;
    int grp = lane >> 3, rr = lane & 7;
    int wm = (wid & 1) * 64, wn = (wid >> 1) * 64;
    int nb = blockIdx.x, mtile = blockIdx.y;       // x fast -> L2 phi pairing
    int n0 = nb * 256;

    if (tid == 0) {
        #pragma unroll
        for (int s = 0; s < NSTG; s++) MBAR_INIT(sb + OFF_MBAR + s * 8, 1);
        asm volatile("fence.proxy.async.shared::cta;" ::: "memory");
    }
    for (int i = tid; i < 256; i += 256) s_bias[i] = g_b1f[n0 + i];
    __syncthreads();

    const uint8_t* phiB = g_phiB + (size_t)mtile * ((size_t)NC1 * A_TS);
    const uint8_t* w1p  = g_W1p + (size_t)nb * B_TS;

    if (tid == 0) {
        #pragma unroll
        for (int s = 0; s < NSTG; s++) {
            uint32_t mb = sb + OFF_MBAR + s * 8;
            MBAR_EXPECT_TX(mb, STG1);
            bulk_g2s(sb + s * STG1, phiB + (size_t)s * A_TS, A_TS, mb);
            bulk_g2s(sb + s * STG1 + A_TS, w1p + (size_t)s * (2 * B_TS), B_TS, mb);
        }
    }

    uint32_t aoff[2][4], bho[2][4], blo[2][4];
    #pragma unroll
    for (int ks = 0; ks < 2; ks++) {
        #pragma unroll
        for (int mt = 0; mt < 4; mt++) {
            int row = ks * 16 + (grp >> 1) * 8 + rr;
            int u = (wm >> 3) + mt * 2 + (grp & 1);
            aoff[ks][mt] = (uint32_t)(row * 256 + ((u ^ rr) << 4));
        }
        #pragma unroll
        for (int p = 0; p < 4; p++) {
            int n = wn + p * 16 + (grp >> 1) * 8 + rr;
            int uh = ks * 2 + (grp & 1);
            bho[ks][p] = (uint32_t)(n * 128 + ((uh ^ (n & 7)) << 4));
            blo[ks][p] = (uint32_t)(n * 128 + (((uh + 4) ^ (n & 7)) << 4));
        }
    }

    float acc[4][8][4];
    #pragma unroll
    for (int mt = 0; mt < 4; mt++)
        #pragma unroll
        for (int nt = 0; nt < 8; nt++)
            #pragma unroll
            for (int q = 0; q < 4; q++) acc[mt][nt][q] = 0.f;

    for (int c = 0; c < NC1; c++) {
        int s = c & (NSTG - 1);
        MBAR_WAIT(sb + OFF_MBAR + s * 8, (c >> 2) & 1);
        uint32_t bA = sb + s * STG1, bB = bA + A_TS;
        bool dolo = (c % 3 == 0);                  // f = 1/3 lo-correction
        #pragma unroll
        for (int ks = 0; ks < 2; ks++) {
            uint32_t ah[4][4], bh[8][2], bl[8][2];
            #pragma unroll
            for (int mt = 0; mt < 4; mt++)
                ldsm4t(ah[mt][0], ah[mt][1], ah[mt][2], ah[mt][3], bA + aoff[ks][mt]);
            #pragma unroll
            for (int p = 0; p < 4; p++)
                ldsm4(bh[2*p][0], bh[2*p][1], bh[2*p+1][0], bh[2*p+1][1], bB + bho[ks][p]);
            if (dolo) {
                #pragma unroll
                for (int p = 0; p < 4; p++)
                    ldsm4(bl[2*p][0], bl[2*p][1], bl[2*p+1][0], bl[2*p+1][1], bB + blo[ks][p]);
            }
            #pragma unroll
            for (int mt = 0; mt < 4; mt++)
                #pragma unroll
                for (int nt = 0; nt < 8; nt++) {
                    mma_h(acc[mt][nt], ah[mt], bh[nt]);
                    if (dolo) mma_h(acc[mt][nt], ah[mt], bl[nt]);
                }
        }
        __syncthreads();
        if (tid == 0 && c + NSTG < NC1) {
            uint32_t mb = sb + OFF_MBAR + s * 8;
            MBAR_EXPECT_TX(mb, STG1);
            bulk_g2s(sb + s * STG1, phiB + (size_t)(c + NSTG) * A_TS, A_TS, mb);
            bulk_g2s(sb + s * STG1 + A_TS, w1p + (size_t)(c + NSTG) * (2 * B_TS), B_TS, mb);
        }
    }

    // ---- epilogue: relu+bias -> smem [n][m] -> packed h1 blocks -------------
    int g = lane >> 2, t = lane & 3;
    __half* se = (__half*)smem;
    #pragma unroll
    for (int mt = 0; mt < 4; mt++) {
        int ml = wm + mt * 16 + g;
        #pragma unroll
        for (int nt = 0; nt < 8; nt++) {
            int ncl = wn + nt * 8 + 2 * t;
            #pragma unroll
            for (int h = 0; h < 2; h++) {
                int mrow = ml + h * 8;
                float v0 = fmaxf(acc[mt][nt][2 * h]     + s_bias[ncl], 0.f);
                float v1 = fmaxf(acc[mt][nt][2 * h + 1] + s_bias[ncl + 1], 0.f);
                se[(size_t)ncl * (RS_E / 2) + mrow]       = __float2half_rn(v0);
                se[(size_t)(ncl + 1) * (RS_E / 2) + mrow] = __float2half_rn(v1);
            }
        }
    }
    __syncthreads();
    size_t h1base = ((size_t)mtile * NC2 + (size_t)nb * 8) * A_TS;
    #pragma unroll
    for (int i = tid; i < 4096; i += 256) {
        int cc = i >> 9, rem = i & 511, k = rem >> 4, u = rem & 15;
        uint32_t saddr = sb + (uint32_t)((cc * 32 + k) * RS_E + u * 16);
        uint32_t r0, r1, r2, r3;
        asm volatile("ld.shared.v4.b32 {%0,%1,%2,%3},[%4];"
            : "=r"(r0), "=r"(r1), "=r"(r2), "=r"(r3) : "r"(saddr));
        *(uint4*)(g_h1B + h1base + (size_t)cc * A_TS + k * 256 + ((u ^ (k & 7)) << 4))
            = make_uint4(r0, r1, r2, r3);
    }
}

// -------------------- GEMM2: bulk ring, C[128m, 96n] --------------------------
__global__ void __launch_bounds__(256, 1) k_gemm2(float* __restrict__ dout) {
    constexpr int OFF_BIAS = NSTG * STG2;          // 81920
    constexpr int OFF_MBAR = OFF_BIAS + 512;
    extern __shared__ char smem[];
    uint32_t sb = smem_u32(smem);
    float* s_bias = (float*)(smem + OFF_BIAS);
    int tid = threadIdx.x, wid = tid >> 5, lane = tid & 31;
    int grp = lane >> 3, rr = lane & 7;
    int wm = (wid & 3) * 32, wn = (wid >> 2) * 48;
    int mtile = blockIdx.x;
    int m0 = mtile * 128;

    if (tid == 0) {
        #pragma unroll
        for (int s = 0; s < NSTG; s++) MBAR_INIT(sb + OFF_MBAR + s * 8, 1);
        asm volatile("fence.proxy.async.shared::cta;" ::: "memory");
    }
    for (int i = tid; i < 96; i += 256) s_bias[i] = g_b2f[i];
    __syncthreads();

    const uint8_t* aB = g_h1B + (size_t)mtile * ((size_t)NC2 * A_TS);

    if (tid == 0) {
        #pragma unroll
        for (int s = 0; s < NSTG; s++) {
            uint32_t mb = sb + OFF_MBAR + s * 8;
            MBAR_EXPECT_TX(mb, STG2);
            bulk_g2s(sb + s * STG2, aB + (size_t)s * A_TS, A_TS, mb);
            bulk_g2s(sb + s * STG2 + A_TS, g_W2p + (size_t)s * B2_TS, B2_TS, mb);
        }
    }

    uint32_t aoff[2][2], bho[2][3], blo[2][3];
    #pragma unroll
    for (int ks = 0; ks < 2; ks++) {
        #pragma unroll
        for (int mt = 0; mt < 2; mt++) {
            int row = ks * 16 + (grp >> 1) * 8 + rr;
            int u = (wm >> 3) + mt * 2 + (grp & 1);
            aoff[ks][mt] = (uint32_t)(row * 256 + ((u ^ rr) << 4));
        }
        #pragma unroll
        for (int p = 0; p < 3; p++) {
            int n = wn + p * 16 + (grp >> 1) * 8 + rr;
            int uh = ks * 2 + (grp & 1);
            bho[ks][p] = (uint32_t)(n * 128 + ((uh ^ (n & 7)) << 4));
            blo[ks][p] = (uint32_t)(n * 128 + (((uh + 4) ^ (n & 7)) << 4));
        }
    }

    float acc[2][6][4];
    #pragma unroll
    for (int mt = 0; mt < 2; mt++)
        #pragma unroll
        for (int nt = 0; nt < 6; nt++)
            #pragma unroll
            for (int q = 0; q < 4; q++) acc[mt][nt][q] = 0.f;

    for (int c = 0; c < NC2; c++) {
        int s = c & (NSTG - 1);
        MBAR_WAIT(sb + OFF_MBAR + s * 8, (c >> 2) & 1);
        uint32_t bA = sb + s * STG2, bB = bA + A_TS;
        #pragma unroll
        for (int ks = 0; ks < 2; ks++) {
            uint32_t ah[2][4], bh[6][2], bl[6][2];
            #pragma unroll
            for (int mt = 0; mt < 2; mt++)
                ldsm4t(ah[mt][0], ah[mt][1], ah[mt][2], ah[mt][3], bA + aoff[ks][mt]);
            #pragma unroll
            for (int p = 0; p < 3; p++) {
                ldsm4(bh[2*p][0], bh[2*p][1], bh[2*p+1][0], bh[2*p+1][1], bB + bho[ks][p]);
                ldsm4(bl[2*p][0], bl[2*p][1], bl[2*p+1][0], bl[2*p+1][1], bB + blo[ks][p]);
            }
            #pragma unroll
            for (int mt = 0; mt < 2; mt++)
                #pragma unroll
                for (int nt = 0; nt < 6; nt++) {
                    mma_h(acc[mt][nt], ah[mt], bh[nt]);
                    mma_h(acc[mt][nt], ah[mt], bl[nt]);
                }
        }
        __syncthreads();
        if (tid == 0 && c + NSTG < NC2) {
            uint32_t mb = sb + OFF_MBAR + s * 8;
            MBAR_EXPECT_TX(mb, STG2);
            bulk_g2s(sb + s * STG2, aB + (size_t)(c + NSTG) * A_TS, A_TS, mb);
            bulk_g2s(sb + s * STG2 + A_TS, g_W2p + (size_t)(c + NSTG) * B2_TS, B2_TS, mb);
        }
    }

    int g = lane >> 2, t = lane & 3;
    #pragma unroll
    for (int mt = 0; mt < 2; mt++) {
        int mr = m0 + wm + mt * 16 + g;
        #pragma unroll
        for (int nt = 0; nt < 6; nt++) {
            int nc = wn + nt * 8 + 2 * t;
            #pragma unroll
            for (int h = 0; h < 2; h++) {
                int mrow = mr + h * 8;
                int b = mrow >> 14, pix = mrow & (HWn - 1);
                dout[(size_t)(b * N2 + nc) * HWn + pix]     = acc[mt][nt][2 * h]     + s_bias[nc];
                dout[(size_t)(b * N2 + nc + 1) * HWn + pix] = acc[mt][nt][2 * h + 1] + s_bias[nc + 1];
            }
        }
    }
}

// -------------------- launch ------------------------------------------------
extern "C" void kernel_launch(void* const* d_in, const int* in_sizes, int n_in,
                              void* d_out, int out_size) {
    (void)in_sizes; (void)n_in; (void)out_size;
    const float* x   = (const float*)d_in[0];
    const float* g1  = (const float*)d_in[1];
    const float* be1 = (const float*)d_in[2];
    const float* mu1 = (const float*)d_in[3];
    const float* va1 = (const float*)d_in[4];
    const float* W1  = (const float*)d_in[5];
    const float* b1  = (const float*)d_in[6];
    const float* g2  = (const float*)d_in[7];
    const float* be2 = (const float*)d_in[8];
    const float* mu2 = (const float*)d_in[9];
    const float* va2 = (const float*)d_in[10];
    const float* W2  = (const float*)d_in[11];
    const float* b2  = (const float*)d_in[12];

    constexpr int S1 = NSTG * STG1 + 1024 + NSTG * 8 + 32;   // ~165 KB
    constexpr int S2 = NSTG * STG2 + 512 + NSTG * 8 + 32;    // ~82.5 KB
    cudaFuncSetAttribute(k_gemm1, cudaFuncAttributeMaxDynamicSharedMemorySize, S1);
    cudaFuncSetAttribute(k_gemm2, cudaFuncAttributeMaxDynamicSharedMemorySize, S2);

    k_folds<<<N1 + N2, 256>>>(W1, b1, g1, be1, mu1, va1, W2, b2, g2, be2, mu2, va2);

    int nsat = Bn * Cn * SATR;
    k_sat_rows<<<(nsat + 127) / 128, 128>>>(x);
    k_sat_cols<<<(nsat + 127) / 128, 128>>>();

    k_features<<<dim3(Mtot / 512, 13), 256>>>(x);

    k_gemm1<<<dim3(2, Mtot / 128), 256, S1>>>();
    k_gemm2<<<dim3(Mtot / 128, 1), 256, S2>>>((float*)d_out);
}